// round 15
// baseline (speedup 1.0000x reference)
#include <cuda_runtime.h>
#include <math.h>

#define NBOX 4096
#define IMH 1080
#define IMW 1920
#define NPIX (IMH * IMW)

typedef unsigned long long ull;

// ---------------- scratch (device globals; no allocation allowed) ----------
__device__ float  g_imgn[3 * IMH * IMW];   // normalized planar image (C,H,W)
__device__ float  g_x1[NBOX * 28 * 121];   // after conv1+pool  [28][11][11]
__device__ float  g_x2[NBOX * 48 * 16];    // after conv2+pool  [48][4][4]
__device__ float  g_x3[NBOX * 576];        // after conv3 flat  [64*3*3]
__device__ float  g_w4t[576 * 128];        // transposed lin4 weights
__device__ ulonglong2 g_w2q[28 * 9 * 12];  // conv2 weights, both co-pairs packed
__device__ float  g_w3t[48 * 64 * 4];      // conv3 weights [ci][co][4] (coalesced)
__device__ float4 g_boxes[NBOX];
__device__ float  g_scores[NBOX];
__device__ int    g_sortidx[NBOX];
__device__ float4 g_sboxes[NBOX];
__device__ int    g_M;
__device__ unsigned long long g_mask[NBOX * 64];

// ---------------- f32x2 packed helpers (sm_103a FFMA2 path) ----------------
__device__ __forceinline__ ull pk(float lo, float hi) {
    ull r; asm("mov.b64 %0, {%1,%2};" : "=l"(r) : "f"(lo), "f"(hi)); return r;
}
__device__ __forceinline__ void upk(ull v, float& lo, float& hi) {
    asm("mov.b64 {%0,%1}, %2;" : "=f"(lo), "=f"(hi) : "l"(v));
}
__device__ __forceinline__ ull ffma2(ull a, ull b, ull c) {
    ull d; asm("fma.rn.f32x2 %0, %1, %2, %3;" : "=l"(d) : "l"(a), "l"(b), "l"(c)); return d;
}

__device__ __forceinline__ int fdiv24(int a) {
    int q = a / 24;
    if ((a % 24) != 0 && a < 0) q--;   // python floor-division semantics
    return q;
}

// ---------------- K0: normalize image (vectorized) + weight prep ------------
__global__ void k_prep(const float* __restrict__ img,
                       const float* __restrict__ w4, const float* __restrict__ w2,
                       const float* __restrict__ w3) {
    int i = blockIdx.x * 256 + threadIdx.x;
    if (i < 576 * 128) {
        int k = i >> 7, j = i & 127;
        g_w4t[i] = w4[j * 576 + k];
    }
    if (i < 3024) {
        int cpg = i % 12, t = i / 12, ci = t / 9, k = t % 9;
        ulonglong2 v;
        v.x = pk(w2[(cpg * 28 + ci) * 9 + k],        w2[((cpg + 24) * 28 + ci) * 9 + k]);
        v.y = pk(w2[((cpg + 12) * 28 + ci) * 9 + k], w2[((cpg + 36) * 28 + ci) * 9 + k]);
        g_w2q[t * 12 + cpg] = v;
    }
    if (i < 12288) {
        int q = i & 3, co = (i >> 2) & 63, ci = i >> 8;
        g_w3t[i] = w3[(co * 48 + ci) * 4 + q];
    }
    // normalize 4 pixels per thread (NPIX divisible by 4)
    if (i < NPIX / 4) {
        const float4* ip = (const float4*)(img + i * 12);
        float4 A = ip[0], B = ip[1], C = ip[2];
        const float o = 127.5f, sc = 0.0078125f;
        float4 R = make_float4((A.x - o) * sc, (A.w - o) * sc, (B.z - o) * sc, (C.y - o) * sc);
        float4 G = make_float4((A.y - o) * sc, (B.x - o) * sc, (B.w - o) * sc, (C.z - o) * sc);
        float4 Bv = make_float4((A.z - o) * sc, (B.y - o) * sc, (C.x - o) * sc, (C.w - o) * sc);
        ((float4*)(g_imgn + i * 4))[0] = R;
        ((float4*)(g_imgn + NPIX + i * 4))[0] = G;
        ((float4*)(g_imgn + 2 * NPIX + i * 4))[0] = Bv;
    }
}

// ---------------- K1: crop+conv1+prelu+maxpool ------------------------------
// block per box, 640 threads, 2 blocks/SM. thread=(cp in 14, s in 22, h in 2):
// channels cp & cp+14, col s, rows h*11..h*11+10. Rolling 3-deep column window.
__global__ void __launch_bounds__(640, 2) k_conv1(const float* __restrict__ bb,
                        const float* __restrict__ w1, const float* __restrict__ b1,
                        const float* __restrict__ a1) {
    extern __shared__ char smem[];
    ull*   s_crop2 = (ull*)smem;                          // 1728 ull (splatted crop)
    float* s_conv  = (float*)(smem + 13824);              // 13552 floats
    ull*   s_wp    = (ull*)(smem + 13824 + 54208);        // 378 ull
    int*   s_ix    = (int*)(smem + 13824 + 54208 + 3024); // 24
    int*   s_iy    = s_ix + 24;                           // 24
    int box = blockIdx.x, tid = threadIdx.x;

    if (tid < 48) {
        int j = tid % 24;
        if (tid < 24) {
            int x1 = (int)bb[box * 4 + 0]; x1 = min(max(x1, 0), IMW);
            int x2 = (int)bb[box * 4 + 2]; x2 = min(max(x2, 0), IMW);
            int v = x1 + fdiv24(j * (x2 - x1));
            s_ix[j] = min(max(v, 0), IMW - 1);
        } else {
            int y1 = (int)bb[box * 4 + 1]; y1 = min(max(y1, 0), IMH);
            int y2 = (int)bb[box * 4 + 3]; y2 = min(max(y2, 0), IMH);
            int v = y1 + fdiv24(j * (y2 - y1));
            s_iy[j] = min(max(v, 0), IMH - 1);
        }
    }
    for (int i = tid; i < 378; i += 640) {
        int cp = i / 27, k = i % 27;
        s_wp[i] = pk(w1[cp * 27 + k], w1[(cp + 14) * 27 + k]);
    }
    __syncthreads();
    for (int i = tid; i < 1728; i += 640) {
        int c = i / 576, rem = i % 576, y = rem / 24, x = rem % 24;
        float v = g_imgn[c * NPIX + s_iy[y] * IMW + s_ix[x]];
        s_crop2[i] = pk(v, v);
    }
    __syncthreads();

    int cp = 0, s = 0, r0 = 0;
    ull acc[11];
    if (tid < 616) {
        cp = tid / 44;
        int rem = tid % 44;
        s = rem >> 1;
        r0 = (rem & 1) * 11;
        ull bv = pk(b1[cp], b1[cp + 14]);
        #pragma unroll
        for (int r = 0; r < 11; r++) acc[r] = bv;
        #pragma unroll
        for (int ci = 0; ci < 3; ci++) {
            const ull* cb = &s_crop2[ci * 576 + r0 * 24 + s];
            const ull* wb = &s_wp[cp * 27 + ci * 9];
            #pragma unroll
            for (int kw = 0; kw < 3; kw++) {
                ull w0 = wb[kw], w1v = wb[3 + kw], w2v = wb[6 + kw];
                ull v0 = cb[0 * 24 + kw];
                ull v1 = cb[1 * 24 + kw];
                #pragma unroll
                for (int r = 0; r < 11; r++) {
                    ull v2 = cb[(r + 2) * 24 + kw];
                    acc[r] = ffma2(v0, w0, acc[r]);
                    acc[r] = ffma2(v1, w1v, acc[r]);
                    acc[r] = ffma2(v2, w2v, acc[r]);
                    v0 = v1; v1 = v2;
                }
            }
        }
    }
    if (tid < 616) {
        float a0 = a1[cp], aH = a1[cp + 14];
        #pragma unroll
        for (int r = 0; r < 11; r++) {
            float lo, hi; upk(acc[r], lo, hi);
            s_conv[cp * 484 + (r0 + r) * 22 + s]        = lo > 0.f ? lo : lo * a0;
            s_conv[(cp + 14) * 484 + (r0 + r) * 22 + s] = hi > 0.f ? hi : hi * aH;
        }
    }
    __syncthreads();
    for (int o = tid; o < 3388; o += 640) {
        int c = o / 121, p = o % 121, ph = p / 11, pw = p % 11;
        float m = -1e30f;
        #pragma unroll
        for (int dr = 0; dr < 3; dr++) {
            int r = 2 * ph - 1 + dr; if (r < 0 || r > 21) continue;
            #pragma unroll
            for (int ds = 0; ds < 3; ds++) {
                int ss = 2 * pw - 1 + ds; if (ss < 0 || ss > 21) continue;
                m = fmaxf(m, s_conv[c * 484 + r * 22 + ss]);
            }
        }
        g_x1[box * 3388 + o] = m;
    }
}

// ---------------- K2: conv2+prelu+maxpool (4-ch threads, LDG.128 weights) ---
__global__ void __launch_bounds__(216, 4) k_conv2(const float* __restrict__ b2,
                                                  const float* __restrict__ a2) {
    __shared__ ull s_in2[3388];
    __shared__ ull s_part[1944];           // h=1 partials; aliased as s_conv after
    float* s_conv = (float*)s_part;        // 3888 floats
    int box = blockIdx.x, tid = threadIdx.x;
    for (int i = tid; i < 3388; i += 216) {
        float v = g_x1[box * 3388 + i];
        s_in2[i] = pk(v, v);
    }
    __syncthreads();
    int half = tid >= 108;
    int t108 = half ? tid - 108 : tid;
    int cpg = t108 / 9, s = t108 % 9;
    ull accA[9], accB[9];
    if (!half) {
        ull bvA = pk(__ldg(&b2[cpg]),      __ldg(&b2[cpg + 24]));
        ull bvB = pk(__ldg(&b2[cpg + 12]), __ldg(&b2[cpg + 36]));
        #pragma unroll
        for (int r = 0; r < 9; r++) { accA[r] = bvA; accB[r] = bvB; }
    } else {
        #pragma unroll
        for (int r = 0; r < 9; r++) { accA[r] = 0ull; accB[r] = 0ull; }
    }
    int ci0 = half ? 14 : 0;
    #pragma unroll 2
    for (int cc = 0; cc < 14; cc++) {
        int ci = ci0 + cc;
        const ulonglong2* wq = &g_w2q[ci * 108 + cpg];
        const ull* ip = &s_in2[ci * 121 + s];
        #pragma unroll
        for (int kw = 0; kw < 3; kw++) {
            ulonglong2 w0 = __ldg(&wq[(0 * 3 + kw) * 12]);
            ulonglong2 w1v = __ldg(&wq[(1 * 3 + kw) * 12]);
            ulonglong2 w2v = __ldg(&wq[(2 * 3 + kw) * 12]);
            #pragma unroll
            for (int t = 0; t < 11; t++) {
                ull sp = ip[t * 11 + kw];
                if (t <= 8) {
                    accA[t] = ffma2(sp, w0.x, accA[t]);
                    accB[t] = ffma2(sp, w0.y, accB[t]);
                }
                if (t >= 1 && t <= 9) {
                    accA[t - 1] = ffma2(sp, w1v.x, accA[t - 1]);
                    accB[t - 1] = ffma2(sp, w1v.y, accB[t - 1]);
                }
                if (t >= 2) {
                    accA[t - 2] = ffma2(sp, w2v.x, accA[t - 2]);
                    accB[t - 2] = ffma2(sp, w2v.y, accB[t - 2]);
                }
            }
        }
    }
    if (half) {
        #pragma unroll
        for (int c = 0; c < 9; c++) {
            s_part[t108 * 18 + c]     = accA[c];
            s_part[t108 * 18 + 9 + c] = accB[c];
        }
    }
    __syncthreads();
    float outv[36];
    if (!half) {
        float aA0 = __ldg(&a2[cpg]),      aA1 = __ldg(&a2[cpg + 24]);
        float aB0 = __ldg(&a2[cpg + 12]), aB1 = __ldg(&a2[cpg + 36]);
        #pragma unroll
        for (int c = 0; c < 9; c++) {
            float lo, hi, plo, phi;
            upk(accA[c], lo, hi);
            upk(s_part[t108 * 18 + c], plo, phi);
            lo += plo; hi += phi;
            outv[c]      = lo > 0.f ? lo : lo * aA0;
            outv[9 + c]  = hi > 0.f ? hi : hi * aA1;
            upk(accB[c], lo, hi);
            upk(s_part[t108 * 18 + 9 + c], plo, phi);
            lo += plo; hi += phi;
            outv[18 + c] = lo > 0.f ? lo : lo * aB0;
            outv[27 + c] = hi > 0.f ? hi : hi * aB1;
        }
    }
    __syncthreads();   // all partial reads done before s_conv overwrites alias
    if (!half) {
        #pragma unroll
        for (int c = 0; c < 9; c++) {
            s_conv[cpg * 81 + c * 9 + s]        = outv[c];
            s_conv[(cpg + 24) * 81 + c * 9 + s] = outv[9 + c];
            s_conv[(cpg + 12) * 81 + c * 9 + s] = outv[18 + c];
            s_conv[(cpg + 36) * 81 + c * 9 + s] = outv[27 + c];
        }
    }
    __syncthreads();
    for (int o = tid; o < 768; o += 216) {
        int co = o / 16, p = o % 16, ph = p / 4, pw = p % 4;
        float m = -1e30f;
        #pragma unroll
        for (int dr = 0; dr < 3; dr++)
            #pragma unroll
            for (int ds = 0; ds < 3; ds++)
                m = fmaxf(m, s_conv[co * 81 + (2 * ph + dr) * 9 + (2 * pw + ds)]);
        g_x2[box * 768 + o] = m;
    }
}

// ---------------- K3: conv3+prelu (f32x2 box-pairs) -------------------------
// 8 boxes per block, 256 threads: thread = (pair pr 0..3, co 0..63) computes
// channel co for boxes box0+pr and box0+pr+4 in packed f32x2.
__global__ void __launch_bounds__(256) k_conv3(const float* __restrict__ b3,
                                               const float* __restrict__ a3) {
    __shared__ ull s_in2[3072];   // [pr][ci][16] packed (box0+pr, box0+pr+4)
    int tid = threadIdx.x;
    int pr = tid >> 6, co = tid & 63;
    int base = blockIdx.x * 6144;
    for (int i = tid; i < 3072; i += 256)
        s_in2[i] = pk(g_x2[base + i], g_x2[base + 3072 + i]);
    __syncthreads();

    ull acc[9];
    float bvs = __ldg(&b3[co]);
    ull bv = pk(bvs, bvs);
    #pragma unroll
    for (int r = 0; r < 9; r++) acc[r] = bv;

    const float4* wt = (const float4*)g_w3t;
    const ulonglong2* qb = (const ulonglong2*)&s_in2[pr * 768];
    #pragma unroll 2
    for (int ci = 0; ci < 48; ci++) {
        float4 w = __ldg(&wt[ci * 64 + co]);
        ull wx = pk(w.x, w.x), wy = pk(w.y, w.y), wz = pk(w.z, w.z), ww = pk(w.w, w.w);
        ull v[4][4];
        #pragma unroll
        for (int r = 0; r < 4; r++) {
            ulonglong2 p0 = qb[ci * 8 + r * 2];
            ulonglong2 p1 = qb[ci * 8 + r * 2 + 1];
            v[r][0] = p0.x; v[r][1] = p0.y; v[r][2] = p1.x; v[r][3] = p1.y;
        }
        #pragma unroll
        for (int r = 0; r < 3; r++)
            #pragma unroll
            for (int s = 0; s < 3; s++) {
                ull t = acc[r * 3 + s];
                t = ffma2(v[r][s],         wx, t);
                t = ffma2(v[r][s + 1],     wy, t);
                t = ffma2(v[r + 1][s],     wz, t);
                t = ffma2(v[r + 1][s + 1], ww, t);
                acc[r * 3 + s] = t;
            }
    }
    float av = __ldg(&a3[co]);
    int box = blockIdx.x * 8 + pr;
    #pragma unroll
    for (int r = 0; r < 9; r++) {
        float lo, hi; upk(acc[r], lo, hi);
        g_x3[box * 576 + co * 9 + r]       = lo > 0.f ? lo : lo * av;
        g_x3[(box + 4) * 576 + co * 9 + r] = hi > 0.f ? hi : hi * av;
    }
}

// ---------------- K4: lin4+prelu, lin5a/b, softmax, box regression ----------
// block = 8 boxes x 128 threads; activations packed (b, b+4) as f32x2,
// built directly from g_x3 (coalesced LDG, no staging copy).
__global__ void k_fc(const float* __restrict__ bb,
                     const float* __restrict__ b4, const float* __restrict__ a4,
                     const float* __restrict__ w5a, const float* __restrict__ b5a,
                     const float* __restrict__ w5b, const float* __restrict__ b5b) {
    __shared__ ull   s_x3p[4 * 576];   // [bp][k]
    __shared__ float s_feat[8 * 128];
    __shared__ float s_dot[48];
    int tid = threadIdx.x;
    int box0 = blockIdx.x * 8;
    #pragma unroll
    for (int bp = 0; bp < 4; bp++) {
        for (int k = tid; k < 576; k += 128) {
            s_x3p[bp * 576 + k] = pk(g_x3[(box0 + bp) * 576 + k],
                                     g_x3[(box0 + bp + 4) * 576 + k]);
        }
    }
    __syncthreads();
    {
        int j = tid;
        ull acc[4];
        float bvs = b4[j];
        ull bv = pk(bvs, bvs);
        #pragma unroll
        for (int b = 0; b < 4; b++) acc[b] = bv;
        #pragma unroll 4
        for (int k = 0; k < 576; k++) {
            float wv = g_w4t[k * 128 + j];
            ull wp2 = pk(wv, wv);
            #pragma unroll
            for (int b = 0; b < 4; b++) acc[b] = ffma2(s_x3p[b * 576 + k], wp2, acc[b]);
        }
        float av = a4[j];
        #pragma unroll
        for (int b = 0; b < 4; b++) {
            float lo, hi; upk(acc[b], lo, hi);
            s_feat[b * 128 + j]       = lo > 0.f ? lo : lo * av;
            s_feat[(b + 4) * 128 + j] = hi > 0.f ? hi : hi * av;
        }
    }
    __syncthreads();
    int warp = tid >> 5, lane = tid & 31;
    for (int d = warp; d < 48; d += 4) {
        int b = d / 6, o = d % 6;
        const float* wrow = (o < 2) ? &w5a[o * 128] : &w5b[(o - 2) * 128];
        float p = 0.f;
        #pragma unroll
        for (int kk = 0; kk < 4; kk++)
            p += s_feat[b * 128 + lane + kk * 32] * __ldg(&wrow[lane + kk * 32]);
        #pragma unroll
        for (int off = 16; off > 0; off >>= 1) p += __shfl_xor_sync(0xffffffffu, p, off);
        if (lane == 0) s_dot[d] = p;
    }
    __syncthreads();
    if (tid < 8) {
        int b = tid, gb = box0 + b;
        float z0 = s_dot[b * 6 + 0] + b5a[0];
        float z1 = s_dot[b * 6 + 1] + b5a[1];
        float mz = fmaxf(z0, z1);
        float e0 = expf(z0 - mz), e1 = expf(z1 - mz);
        g_scores[gb] = e1 / (e0 + e1);
        float4 B = ((const float4*)bb)[gb];
        float bw = B.z - B.x, bh = B.w - B.y;
        float4 nb;
        nb.x = B.x + (s_dot[b * 6 + 2] + b5b[0]) * bw;
        nb.y = B.y + (s_dot[b * 6 + 3] + b5b[1]) * bh;
        nb.z = B.z + (s_dot[b * 6 + 4] + b5b[2]) * bw;
        nb.w = B.w + (s_dot[b * 6 + 5] + b5b[3]) * bh;
        g_boxes[gb] = nb;
    }
}

// ---------------- K5: compact valid + adaptive bitonic sort -----------------
__global__ void k_sort() {
    __shared__ unsigned long long key[4096];
    __shared__ int s_cnt, s_P;
    int tid = threadIdx.x;
    if (tid == 0) s_cnt = 0;
    __syncthreads();
    for (int i = tid; i < 4096; i += 1024) {
        float sc = g_scores[i];
        if (sc >= 0.7f) {
            unsigned u = __float_as_uint(sc);
            unsigned m = (u & 0x80000000u) ? ~u : (u | 0x80000000u);  // monotone map
            int pos = atomicAdd(&s_cnt, 1);
            key[pos] = ((unsigned long long)(~m) << 32) | (unsigned)i;  // asc = desc score, asc idx
        }
    }
    __syncthreads();
    int M = s_cnt;
    if (tid == 0) {
        g_M = M;
        int P = 2;
        while (P < M) P <<= 1;
        s_P = P;
    }
    __syncthreads();
    int P = s_P;
    for (int i = M + tid; i < P; i += 1024) key[i] = 0xFFFFFFFFFFFFFFFFull;
    __syncthreads();
    for (int k = 2; k <= P; k <<= 1) {
        for (int j = k >> 1; j > 0; j >>= 1) {
            for (int t = tid; t < P; t += 1024) {
                int ixj = t ^ j;
                if (ixj > t) {
                    bool up = ((t & k) == 0);
                    unsigned long long a = key[t], b = key[ixj];
                    if ((a > b) == up) { key[t] = b; key[ixj] = a; }
                }
            }
            __syncthreads();
        }
    }
    for (int i = tid; i < M; i += 1024) {
        int idx = (int)(unsigned)key[i];
        g_sortidx[i] = idx;
        g_sboxes[i] = g_boxes[idx];
    }
}

// ---------------- K6: pairwise IOU bitmask over valid prefix ----------------
__global__ void k_mask() {
    int gid = blockIdx.x * 256 + threadIdx.x;
    int row = gid >> 6, word = gid & 63;
    int M = g_M;
    if (row >= M) return;
    int nw = (M + 63) >> 6;
    if (word >= nw) return;
    float4 bi = g_sboxes[row];
    float ai = fmaxf(bi.z - bi.x, 0.f) * fmaxf(bi.w - bi.y, 0.f);
    unsigned long long m = 0;
    int j0 = word * 64;
    for (int t = 0; t < 64; t++) {
        int j = j0 + t;
        if (j <= row || j >= M) continue;
        float4 bj = g_sboxes[j];
        float xx1 = fmaxf(bi.x, bj.x), yy1 = fmaxf(bi.y, bj.y);
        float xx2 = fminf(bi.z, bj.z), yy2 = fminf(bi.w, bj.w);
        float inter = fmaxf(xx2 - xx1, 0.f) * fmaxf(yy2 - yy1, 0.f);
        float aj = fmaxf(bj.z - bj.x, 0.f) * fmaxf(bj.w - bj.y, 0.f);
        float iou = inter / fmaxf(ai + aj - inter, 1e-12f);
        if (iou > 0.5f) m |= (1ull << t);
    }
    g_mask[row * 64 + word] = m;
}

// ---------------- K7: NMS scan, zero-fill, scatter kept ---------------------
__global__ void k_scan(float* __restrict__ out) {
    __shared__ unsigned char s_keep[4096];
    int tid = threadIdx.x;
    int M = g_M;
    if (tid < 32) {
        ull rlo = 0, rhi = 0;   // lane t owns words t and 32+t (4096 bits)
        ull blo[8], bhi[8];
        #pragma unroll
        for (int k = 0; k < 8; k++) {
            if (k < M) { blo[k] = g_mask[k * 64 + tid]; bhi[k] = g_mask[k * 64 + 32 + tid]; }
        }
        for (int ib = 0; ib < M; ib += 8) {
            #pragma unroll
            for (int k = 0; k < 8; k++) {
                int i = ib + k;
                if (i < M) {
                    ull clo = blo[k], chi = bhi[k];
                    if (i + 8 < M) {
                        blo[k] = g_mask[(i + 8) * 64 + tid];
                        bhi[k] = g_mask[(i + 8) * 64 + 32 + tid];
                    }
                    int w = i >> 6, b = i & 63;
                    ull cand = (w < 32) ? rlo : rhi;
                    ull rv = __shfl_sync(0xffffffffu, cand, w & 31);
                    int sup = (int)((rv >> b) & 1ull);
                    if (!sup) { rlo |= clo; rhi |= chi; }
                    if (tid == 0) s_keep[i] = (unsigned char)(!sup);
                }
            }
        }
    }
    __syncthreads();
    for (int i = tid; i < 4096; i += blockDim.x)
        ((float4*)out)[i] = make_float4(0.f, 0.f, 0.f, 0.f);
    __syncthreads();
    for (int i = tid; i < M; i += blockDim.x) {
        if (s_keep[i]) ((float4*)out)[g_sortidx[i]] = g_sboxes[i];
    }
}

// ---------------- launch ----------------------------------------------------
extern "C" void kernel_launch(void* const* d_in, const int* in_sizes, int n_in,
                              void* d_out, int out_size) {
    const float* img  = (const float*)d_in[0];
    const float* bb   = (const float*)d_in[1];
    const float* w1   = (const float*)d_in[2];
    const float* b1   = (const float*)d_in[3];
    const float* a1   = (const float*)d_in[4];
    const float* w2   = (const float*)d_in[5];
    const float* b2   = (const float*)d_in[6];
    const float* a2   = (const float*)d_in[7];
    const float* w3   = (const float*)d_in[8];
    const float* b3   = (const float*)d_in[9];
    const float* a3   = (const float*)d_in[10];
    const float* w4   = (const float*)d_in[11];
    const float* b4   = (const float*)d_in[12];
    const float* a4   = (const float*)d_in[13];
    const float* w5a  = (const float*)d_in[14];
    const float* b5a  = (const float*)d_in[15];
    const float* w5b  = (const float*)d_in[16];
    const float* b5b  = (const float*)d_in[17];
    float* out = (float*)d_out;

    static int smem_set = 0;
    if (!smem_set) {
        cudaFuncSetAttribute(k_conv1, cudaFuncAttributeMaxDynamicSharedMemorySize, 71296);
        smem_set = 1;
    }

    k_prep <<<(NPIX / 4 + 255) / 256, 256>>>(img, w4, w2, w3);
    k_conv1<<<NBOX, 640, 71296>>>(bb, w1, b1, a1);
    k_conv2<<<NBOX, 216>>>(b2, a2);
    k_conv3<<<NBOX / 8, 256>>>(b3, a3);
    k_fc   <<<NBOX / 8, 128>>>(bb, b4, a4, w5a, b5a, w5b, b5b);
    k_sort <<<1, 1024>>>();
    k_mask <<<1024, 256>>>();
    k_scan <<<1, 256>>>(out);
}

// round 16
// speedup vs baseline: 1.0499x; 1.0499x over previous
#include <cuda_runtime.h>
#include <math.h>

#define NBOX 4096
#define IMH 1080
#define IMW 1920
#define NPIX (IMH * IMW)

typedef unsigned long long ull;

// ---------------- scratch (device globals; no allocation allowed) ----------
__device__ float  g_imgn[3 * IMH * IMW];   // normalized planar image (C,H,W)
__device__ float  g_x1[NBOX * 28 * 121];   // after conv1+pool  [28][11][11]
__device__ float  g_x2[NBOX * 48 * 16];    // after conv2+pool  [48][4][4]
__device__ float  g_x3[NBOX * 576];        // after conv3 flat  [64*3*3]
__device__ float  g_w4t[576 * 128];        // transposed lin4 weights
__device__ ulonglong2 g_w2q[28 * 9 * 12];  // conv2 weights, both co-pairs packed
__device__ float  g_w3t[48 * 64 * 4];      // conv3 weights [ci][co][4] (coalesced)
__device__ float4 g_boxes[NBOX];
__device__ float  g_scores[NBOX];
__device__ int    g_sortidx[NBOX];
__device__ float4 g_sboxes[NBOX];
__device__ int    g_M;
__device__ unsigned long long g_mask[NBOX * 64];

// ---------------- f32x2 packed helpers (sm_103a FFMA2 path) ----------------
__device__ __forceinline__ ull pk(float lo, float hi) {
    ull r; asm("mov.b64 %0, {%1,%2};" : "=l"(r) : "f"(lo), "f"(hi)); return r;
}
__device__ __forceinline__ void upk(ull v, float& lo, float& hi) {
    asm("mov.b64 {%0,%1}, %2;" : "=f"(lo), "=f"(hi) : "l"(v));
}
__device__ __forceinline__ ull ffma2(ull a, ull b, ull c) {
    ull d; asm("fma.rn.f32x2 %0, %1, %2, %3;" : "=l"(d) : "l"(a), "l"(b), "l"(c)); return d;
}

__device__ __forceinline__ int fdiv24(int a) {
    int q = a / 24;
    if ((a % 24) != 0 && a < 0) q--;   // python floor-division semantics
    return q;
}

// ---------------- K0: normalize image (vectorized) + weight prep ------------
__global__ void k_prep(const float* __restrict__ img,
                       const float* __restrict__ w4, const float* __restrict__ w2,
                       const float* __restrict__ w3) {
    int i = blockIdx.x * 256 + threadIdx.x;
    if (i < 576 * 128) {
        int k = i >> 7, j = i & 127;
        g_w4t[i] = w4[j * 576 + k];
    }
    if (i < 3024) {
        int cpg = i % 12, t = i / 12, ci = t / 9, k = t % 9;
        ulonglong2 v;
        v.x = pk(w2[(cpg * 28 + ci) * 9 + k],        w2[((cpg + 24) * 28 + ci) * 9 + k]);
        v.y = pk(w2[((cpg + 12) * 28 + ci) * 9 + k], w2[((cpg + 36) * 28 + ci) * 9 + k]);
        g_w2q[t * 12 + cpg] = v;
    }
    if (i < 12288) {
        int q = i & 3, co = (i >> 2) & 63, ci = i >> 8;
        g_w3t[i] = w3[(co * 48 + ci) * 4 + q];
    }
    // normalize 4 pixels per thread (NPIX divisible by 4)
    if (i < NPIX / 4) {
        const float4* ip = (const float4*)(img + i * 12);
        float4 A = ip[0], B = ip[1], C = ip[2];
        const float o = 127.5f, sc = 0.0078125f;
        float4 R = make_float4((A.x - o) * sc, (A.w - o) * sc, (B.z - o) * sc, (C.y - o) * sc);
        float4 G = make_float4((A.y - o) * sc, (B.x - o) * sc, (B.w - o) * sc, (C.z - o) * sc);
        float4 Bv = make_float4((A.z - o) * sc, (B.y - o) * sc, (C.x - o) * sc, (C.w - o) * sc);
        ((float4*)(g_imgn + i * 4))[0] = R;
        ((float4*)(g_imgn + NPIX + i * 4))[0] = G;
        ((float4*)(g_imgn + 2 * NPIX + i * 4))[0] = Bv;
    }
}

// ---------------- K1: crop+conv1+prelu+maxpool ------------------------------
// block per box, 640 threads, 2 blocks/SM. thread=(cp in 14, s in 22, h in 2):
// channels cp & cp+14, col s, rows h*11..h*11+10. Rolling 3-deep column window.
__global__ void __launch_bounds__(640, 2) k_conv1(const float* __restrict__ bb,
                        const float* __restrict__ w1, const float* __restrict__ b1,
                        const float* __restrict__ a1) {
    extern __shared__ char smem[];
    ull*   s_crop2 = (ull*)smem;                          // 1728 ull (splatted crop)
    float* s_conv  = (float*)(smem + 13824);              // 13552 floats
    ull*   s_wp    = (ull*)(smem + 13824 + 54208);        // 378 ull
    int*   s_ix    = (int*)(smem + 13824 + 54208 + 3024); // 24
    int*   s_iy    = s_ix + 24;                           // 24
    int box = blockIdx.x, tid = threadIdx.x;

    if (tid < 48) {
        int j = tid % 24;
        if (tid < 24) {
            int x1 = (int)bb[box * 4 + 0]; x1 = min(max(x1, 0), IMW);
            int x2 = (int)bb[box * 4 + 2]; x2 = min(max(x2, 0), IMW);
            int v = x1 + fdiv24(j * (x2 - x1));
            s_ix[j] = min(max(v, 0), IMW - 1);
        } else {
            int y1 = (int)bb[box * 4 + 1]; y1 = min(max(y1, 0), IMH);
            int y2 = (int)bb[box * 4 + 3]; y2 = min(max(y2, 0), IMH);
            int v = y1 + fdiv24(j * (y2 - y1));
            s_iy[j] = min(max(v, 0), IMH - 1);
        }
    }
    for (int i = tid; i < 378; i += 640) {
        int cp = i / 27, k = i % 27;
        s_wp[i] = pk(w1[cp * 27 + k], w1[(cp + 14) * 27 + k]);
    }
    __syncthreads();
    for (int i = tid; i < 1728; i += 640) {
        int c = i / 576, rem = i % 576, y = rem / 24, x = rem % 24;
        float v = g_imgn[c * NPIX + s_iy[y] * IMW + s_ix[x]];
        s_crop2[i] = pk(v, v);
    }
    __syncthreads();

    int cp = 0, s = 0, r0 = 0;
    ull acc[11];
    if (tid < 616) {
        cp = tid / 44;
        int rem = tid % 44;
        s = rem >> 1;
        r0 = (rem & 1) * 11;
        ull bv = pk(b1[cp], b1[cp + 14]);
        #pragma unroll
        for (int r = 0; r < 11; r++) acc[r] = bv;
        #pragma unroll
        for (int ci = 0; ci < 3; ci++) {
            const ull* cb = &s_crop2[ci * 576 + r0 * 24 + s];
            const ull* wb = &s_wp[cp * 27 + ci * 9];
            #pragma unroll
            for (int kw = 0; kw < 3; kw++) {
                ull w0 = wb[kw], w1v = wb[3 + kw], w2v = wb[6 + kw];
                ull v0 = cb[0 * 24 + kw];
                ull v1 = cb[1 * 24 + kw];
                #pragma unroll
                for (int r = 0; r < 11; r++) {
                    ull v2 = cb[(r + 2) * 24 + kw];
                    acc[r] = ffma2(v0, w0, acc[r]);
                    acc[r] = ffma2(v1, w1v, acc[r]);
                    acc[r] = ffma2(v2, w2v, acc[r]);
                    v0 = v1; v1 = v2;
                }
            }
        }
    }
    if (tid < 616) {
        float a0 = a1[cp], aH = a1[cp + 14];
        #pragma unroll
        for (int r = 0; r < 11; r++) {
            float lo, hi; upk(acc[r], lo, hi);
            s_conv[cp * 484 + (r0 + r) * 22 + s]        = lo > 0.f ? lo : lo * a0;
            s_conv[(cp + 14) * 484 + (r0 + r) * 22 + s] = hi > 0.f ? hi : hi * aH;
        }
    }
    __syncthreads();
    for (int o = tid; o < 3388; o += 640) {
        int c = o / 121, p = o % 121, ph = p / 11, pw = p % 11;
        float m = -1e30f;
        #pragma unroll
        for (int dr = 0; dr < 3; dr++) {
            int r = 2 * ph - 1 + dr; if (r < 0 || r > 21) continue;
            #pragma unroll
            for (int ds = 0; ds < 3; ds++) {
                int ss = 2 * pw - 1 + ds; if (ss < 0 || ss > 21) continue;
                m = fmaxf(m, s_conv[c * 484 + r * 22 + ss]);
            }
        }
        g_x1[box * 3388 + o] = m;
    }
}

// ---------------- K2: conv2+prelu+maxpool (4-ch threads, LDG.128 weights) ---
__global__ void __launch_bounds__(216, 4) k_conv2(const float* __restrict__ b2,
                                                  const float* __restrict__ a2) {
    __shared__ ull s_in2[3388];
    __shared__ ull s_part[1944];           // h=1 partials; aliased as s_conv after
    float* s_conv = (float*)s_part;        // 3888 floats
    int box = blockIdx.x, tid = threadIdx.x;
    for (int i = tid; i < 3388; i += 216) {
        float v = g_x1[box * 3388 + i];
        s_in2[i] = pk(v, v);
    }
    __syncthreads();
    int half = tid >= 108;
    int t108 = half ? tid - 108 : tid;
    int cpg = t108 / 9, s = t108 % 9;
    ull accA[9], accB[9];
    if (!half) {
        ull bvA = pk(__ldg(&b2[cpg]),      __ldg(&b2[cpg + 24]));
        ull bvB = pk(__ldg(&b2[cpg + 12]), __ldg(&b2[cpg + 36]));
        #pragma unroll
        for (int r = 0; r < 9; r++) { accA[r] = bvA; accB[r] = bvB; }
    } else {
        #pragma unroll
        for (int r = 0; r < 9; r++) { accA[r] = 0ull; accB[r] = 0ull; }
    }
    int ci0 = half ? 14 : 0;
    #pragma unroll 2
    for (int cc = 0; cc < 14; cc++) {
        int ci = ci0 + cc;
        const ulonglong2* wq = &g_w2q[ci * 108 + cpg];
        const ull* ip = &s_in2[ci * 121 + s];
        #pragma unroll
        for (int kw = 0; kw < 3; kw++) {
            ulonglong2 w0 = __ldg(&wq[(0 * 3 + kw) * 12]);
            ulonglong2 w1v = __ldg(&wq[(1 * 3 + kw) * 12]);
            ulonglong2 w2v = __ldg(&wq[(2 * 3 + kw) * 12]);
            #pragma unroll
            for (int t = 0; t < 11; t++) {
                ull sp = ip[t * 11 + kw];
                if (t <= 8) {
                    accA[t] = ffma2(sp, w0.x, accA[t]);
                    accB[t] = ffma2(sp, w0.y, accB[t]);
                }
                if (t >= 1 && t <= 9) {
                    accA[t - 1] = ffma2(sp, w1v.x, accA[t - 1]);
                    accB[t - 1] = ffma2(sp, w1v.y, accB[t - 1]);
                }
                if (t >= 2) {
                    accA[t - 2] = ffma2(sp, w2v.x, accA[t - 2]);
                    accB[t - 2] = ffma2(sp, w2v.y, accB[t - 2]);
                }
            }
        }
    }
    if (half) {
        #pragma unroll
        for (int c = 0; c < 9; c++) {
            s_part[t108 * 18 + c]     = accA[c];
            s_part[t108 * 18 + 9 + c] = accB[c];
        }
    }
    __syncthreads();
    float outv[36];
    if (!half) {
        float aA0 = __ldg(&a2[cpg]),      aA1 = __ldg(&a2[cpg + 24]);
        float aB0 = __ldg(&a2[cpg + 12]), aB1 = __ldg(&a2[cpg + 36]);
        #pragma unroll
        for (int c = 0; c < 9; c++) {
            float lo, hi, plo, phi;
            upk(accA[c], lo, hi);
            upk(s_part[t108 * 18 + c], plo, phi);
            lo += plo; hi += phi;
            outv[c]      = lo > 0.f ? lo : lo * aA0;
            outv[9 + c]  = hi > 0.f ? hi : hi * aA1;
            upk(accB[c], lo, hi);
            upk(s_part[t108 * 18 + 9 + c], plo, phi);
            lo += plo; hi += phi;
            outv[18 + c] = lo > 0.f ? lo : lo * aB0;
            outv[27 + c] = hi > 0.f ? hi : hi * aB1;
        }
    }
    __syncthreads();   // all partial reads done before s_conv overwrites alias
    if (!half) {
        #pragma unroll
        for (int c = 0; c < 9; c++) {
            s_conv[cpg * 81 + c * 9 + s]        = outv[c];
            s_conv[(cpg + 24) * 81 + c * 9 + s] = outv[9 + c];
            s_conv[(cpg + 12) * 81 + c * 9 + s] = outv[18 + c];
            s_conv[(cpg + 36) * 81 + c * 9 + s] = outv[27 + c];
        }
    }
    __syncthreads();
    for (int o = tid; o < 768; o += 216) {
        int co = o / 16, p = o % 16, ph = p / 4, pw = p % 4;
        float m = -1e30f;
        #pragma unroll
        for (int dr = 0; dr < 3; dr++)
            #pragma unroll
            for (int ds = 0; ds < 3; ds++)
                m = fmaxf(m, s_conv[co * 81 + (2 * ph + dr) * 9 + (2 * pw + ds)]);
        g_x2[box * 768 + o] = m;
    }
}

// ---------------- K3: conv3+prelu (f32x2 box-pairs, 4 boxes/block) ----------
// 4 boxes per block, 128 threads: thread = (pair pr 0..1, co 0..63) computes
// channel co for boxes box0+pr and box0+pr+2 in packed f32x2.
__global__ void __launch_bounds__(128) k_conv3(const float* __restrict__ b3,
                                               const float* __restrict__ a3) {
    __shared__ ull s_in2[1536];   // [pr][ci][16] packed (box0+pr, box0+pr+2)
    int tid = threadIdx.x;
    int pr = tid >> 6, co = tid & 63;
    int base = blockIdx.x * 3072;
    for (int i = tid; i < 1536; i += 128)
        s_in2[i] = pk(g_x2[base + i], g_x2[base + 1536 + i]);
    __syncthreads();

    ull acc[9];
    float bvs = __ldg(&b3[co]);
    ull bv = pk(bvs, bvs);
    #pragma unroll
    for (int r = 0; r < 9; r++) acc[r] = bv;

    const float4* wt = (const float4*)g_w3t;
    const ulonglong2* qb = (const ulonglong2*)&s_in2[pr * 768];
    #pragma unroll 2
    for (int ci = 0; ci < 48; ci++) {
        float4 w = __ldg(&wt[ci * 64 + co]);
        ull wx = pk(w.x, w.x), wy = pk(w.y, w.y), wz = pk(w.z, w.z), ww = pk(w.w, w.w);
        ull v[4][4];
        #pragma unroll
        for (int r = 0; r < 4; r++) {
            ulonglong2 p0 = qb[ci * 8 + r * 2];
            ulonglong2 p1 = qb[ci * 8 + r * 2 + 1];
            v[r][0] = p0.x; v[r][1] = p0.y; v[r][2] = p1.x; v[r][3] = p1.y;
        }
        #pragma unroll
        for (int r = 0; r < 3; r++)
            #pragma unroll
            for (int s = 0; s < 3; s++) {
                ull t = acc[r * 3 + s];
                t = ffma2(v[r][s],         wx, t);
                t = ffma2(v[r][s + 1],     wy, t);
                t = ffma2(v[r + 1][s],     wz, t);
                t = ffma2(v[r + 1][s + 1], ww, t);
                acc[r * 3 + s] = t;
            }
    }
    float av = __ldg(&a3[co]);
    int box = blockIdx.x * 4 + pr;
    #pragma unroll
    for (int r = 0; r < 9; r++) {
        float lo, hi; upk(acc[r], lo, hi);
        g_x3[box * 576 + co * 9 + r]       = lo > 0.f ? lo : lo * av;
        g_x3[(box + 2) * 576 + co * 9 + r] = hi > 0.f ? hi : hi * av;
    }
}

// ---------------- K4: lin4+prelu, lin5a/b, softmax, box regression ----------
// block = 8 boxes x 128 threads; activations packed (b, b+4) as f32x2,
// built directly from g_x3 (coalesced LDG, no staging copy).
__global__ void k_fc(const float* __restrict__ bb,
                     const float* __restrict__ b4, const float* __restrict__ a4,
                     const float* __restrict__ w5a, const float* __restrict__ b5a,
                     const float* __restrict__ w5b, const float* __restrict__ b5b) {
    __shared__ ull   s_x3p[4 * 576];   // [bp][k]
    __shared__ float s_feat[8 * 128];
    __shared__ float s_dot[48];
    int tid = threadIdx.x;
    int box0 = blockIdx.x * 8;
    #pragma unroll
    for (int bp = 0; bp < 4; bp++) {
        for (int k = tid; k < 576; k += 128) {
            s_x3p[bp * 576 + k] = pk(g_x3[(box0 + bp) * 576 + k],
                                     g_x3[(box0 + bp + 4) * 576 + k]);
        }
    }
    __syncthreads();
    {
        int j = tid;
        ull acc[4];
        float bvs = b4[j];
        ull bv = pk(bvs, bvs);
        #pragma unroll
        for (int b = 0; b < 4; b++) acc[b] = bv;
        #pragma unroll 4
        for (int k = 0; k < 576; k++) {
            float wv = g_w4t[k * 128 + j];
            ull wp2 = pk(wv, wv);
            #pragma unroll
            for (int b = 0; b < 4; b++) acc[b] = ffma2(s_x3p[b * 576 + k], wp2, acc[b]);
        }
        float av = a4[j];
        #pragma unroll
        for (int b = 0; b < 4; b++) {
            float lo, hi; upk(acc[b], lo, hi);
            s_feat[b * 128 + j]       = lo > 0.f ? lo : lo * av;
            s_feat[(b + 4) * 128 + j] = hi > 0.f ? hi : hi * av;
        }
    }
    __syncthreads();
    int warp = tid >> 5, lane = tid & 31;
    for (int d = warp; d < 48; d += 4) {
        int b = d / 6, o = d % 6;
        const float* wrow = (o < 2) ? &w5a[o * 128] : &w5b[(o - 2) * 128];
        float p = 0.f;
        #pragma unroll
        for (int kk = 0; kk < 4; kk++)
            p += s_feat[b * 128 + lane + kk * 32] * __ldg(&wrow[lane + kk * 32]);
        #pragma unroll
        for (int off = 16; off > 0; off >>= 1) p += __shfl_xor_sync(0xffffffffu, p, off);
        if (lane == 0) s_dot[d] = p;
    }
    __syncthreads();
    if (tid < 8) {
        int b = tid, gb = box0 + b;
        float z0 = s_dot[b * 6 + 0] + b5a[0];
        float z1 = s_dot[b * 6 + 1] + b5a[1];
        float mz = fmaxf(z0, z1);
        float e0 = expf(z0 - mz), e1 = expf(z1 - mz);
        g_scores[gb] = e1 / (e0 + e1);
        float4 B = ((const float4*)bb)[gb];
        float bw = B.z - B.x, bh = B.w - B.y;
        float4 nb;
        nb.x = B.x + (s_dot[b * 6 + 2] + b5b[0]) * bw;
        nb.y = B.y + (s_dot[b * 6 + 3] + b5b[1]) * bh;
        nb.z = B.z + (s_dot[b * 6 + 4] + b5b[2]) * bw;
        nb.w = B.w + (s_dot[b * 6 + 5] + b5b[3]) * bh;
        g_boxes[gb] = nb;
    }
}

// ---------------- K5: compact valid + adaptive bitonic sort -----------------
__global__ void k_sort() {
    __shared__ unsigned long long key[4096];
    __shared__ int s_cnt, s_P;
    int tid = threadIdx.x;
    if (tid == 0) s_cnt = 0;
    __syncthreads();
    for (int i = tid; i < 4096; i += 1024) {
        float sc = g_scores[i];
        if (sc >= 0.7f) {
            unsigned u = __float_as_uint(sc);
            unsigned m = (u & 0x80000000u) ? ~u : (u | 0x80000000u);  // monotone map
            int pos = atomicAdd(&s_cnt, 1);
            key[pos] = ((unsigned long long)(~m) << 32) | (unsigned)i;  // asc = desc score, asc idx
        }
    }
    __syncthreads();
    int M = s_cnt;
    if (tid == 0) {
        g_M = M;
        int P = 2;
        while (P < M) P <<= 1;
        s_P = P;
    }
    __syncthreads();
    int P = s_P;
    for (int i = M + tid; i < P; i += 1024) key[i] = 0xFFFFFFFFFFFFFFFFull;
    __syncthreads();
    for (int k = 2; k <= P; k <<= 1) {
        for (int j = k >> 1; j > 0; j >>= 1) {
            for (int t = tid; t < P; t += 1024) {
                int ixj = t ^ j;
                if (ixj > t) {
                    bool up = ((t & k) == 0);
                    unsigned long long a = key[t], b = key[ixj];
                    if ((a > b) == up) { key[t] = b; key[ixj] = a; }
                }
            }
            __syncthreads();
        }
    }
    for (int i = tid; i < M; i += 1024) {
        int idx = (int)(unsigned)key[i];
        g_sortidx[i] = idx;
        g_sboxes[i] = g_boxes[idx];
    }
}

// ---------------- K6: pairwise IOU bitmask over valid prefix ----------------
__global__ void k_mask() {
    int gid = blockIdx.x * 256 + threadIdx.x;
    int row = gid >> 6, word = gid & 63;
    int M = g_M;
    if (row >= M) return;
    int nw = (M + 63) >> 6;
    if (word >= nw) return;
    float4 bi = g_sboxes[row];
    float ai = fmaxf(bi.z - bi.x, 0.f) * fmaxf(bi.w - bi.y, 0.f);
    unsigned long long m = 0;
    int j0 = word * 64;
    for (int t = 0; t < 64; t++) {
        int j = j0 + t;
        if (j <= row || j >= M) continue;
        float4 bj = g_sboxes[j];
        float xx1 = fmaxf(bi.x, bj.x), yy1 = fmaxf(bi.y, bj.y);
        float xx2 = fminf(bi.z, bj.z), yy2 = fminf(bi.w, bj.w);
        float inter = fmaxf(xx2 - xx1, 0.f) * fmaxf(yy2 - yy1, 0.f);
        float aj = fmaxf(bj.z - bj.x, 0.f) * fmaxf(bj.w - bj.y, 0.f);
        float iou = inter / fmaxf(ai + aj - inter, 1e-12f);
        if (iou > 0.5f) m |= (1ull << t);
    }
    g_mask[row * 64 + word] = m;
}

// ---------------- K7: NMS scan, zero-fill, scatter kept ---------------------
__global__ void k_scan(float* __restrict__ out) {
    __shared__ unsigned char s_keep[4096];
    int tid = threadIdx.x;
    int M = g_M;
    if (tid < 32) {
        ull rlo = 0, rhi = 0;   // lane t owns words t and 32+t (4096 bits)
        ull blo[8], bhi[8];
        #pragma unroll
        for (int k = 0; k < 8; k++) {
            if (k < M) { blo[k] = g_mask[k * 64 + tid]; bhi[k] = g_mask[k * 64 + 32 + tid]; }
        }
        for (int ib = 0; ib < M; ib += 8) {
            #pragma unroll
            for (int k = 0; k < 8; k++) {
                int i = ib + k;
                if (i < M) {
                    ull clo = blo[k], chi = bhi[k];
                    if (i + 8 < M) {
                        blo[k] = g_mask[(i + 8) * 64 + tid];
                        bhi[k] = g_mask[(i + 8) * 64 + 32 + tid];
                    }
                    int w = i >> 6, b = i & 63;
                    ull cand = (w < 32) ? rlo : rhi;
                    ull rv = __shfl_sync(0xffffffffu, cand, w & 31);
                    int sup = (int)((rv >> b) & 1ull);
                    if (!sup) { rlo |= clo; rhi |= chi; }
                    if (tid == 0) s_keep[i] = (unsigned char)(!sup);
                }
            }
        }
    }
    __syncthreads();
    for (int i = tid; i < 4096; i += blockDim.x)
        ((float4*)out)[i] = make_float4(0.f, 0.f, 0.f, 0.f);
    __syncthreads();
    for (int i = tid; i < M; i += blockDim.x) {
        if (s_keep[i]) ((float4*)out)[g_sortidx[i]] = g_sboxes[i];
    }
}

// ---------------- launch ----------------------------------------------------
extern "C" void kernel_launch(void* const* d_in, const int* in_sizes, int n_in,
                              void* d_out, int out_size) {
    const float* img  = (const float*)d_in[0];
    const float* bb   = (const float*)d_in[1];
    const float* w1   = (const float*)d_in[2];
    const float* b1   = (const float*)d_in[3];
    const float* a1   = (const float*)d_in[4];
    const float* w2   = (const float*)d_in[5];
    const float* b2   = (const float*)d_in[6];
    const float* a2   = (const float*)d_in[7];
    const float* w3   = (const float*)d_in[8];
    const float* b3   = (const float*)d_in[9];
    const float* a3   = (const float*)d_in[10];
    const float* w4   = (const float*)d_in[11];
    const float* b4   = (const float*)d_in[12];
    const float* a4   = (const float*)d_in[13];
    const float* w5a  = (const float*)d_in[14];
    const float* b5a  = (const float*)d_in[15];
    const float* w5b  = (const float*)d_in[16];
    const float* b5b  = (const float*)d_in[17];
    float* out = (float*)d_out;

    static int smem_set = 0;
    if (!smem_set) {
        cudaFuncSetAttribute(k_conv1, cudaFuncAttributeMaxDynamicSharedMemorySize, 71296);
        smem_set = 1;
    }

    k_prep <<<(NPIX / 4 + 255) / 256, 256>>>(img, w4, w2, w3);
    k_conv1<<<NBOX, 640, 71296>>>(bb, w1, b1, a1);
    k_conv2<<<NBOX, 216>>>(b2, a2);
    k_conv3<<<NBOX / 4, 128>>>(b3, a3);
    k_fc   <<<NBOX / 8, 128>>>(bb, b4, a4, w5a, b5a, w5b, b5b);
    k_sort <<<1, 1024>>>();
    k_mask <<<1024, 256>>>();
    k_scan <<<1, 256>>>(out);
}

// round 17
// speedup vs baseline: 1.0507x; 1.0008x over previous
#include <cuda_runtime.h>
#include <math.h>

#define NBOX 4096
#define IMH 1080
#define IMW 1920
#define NPIX (IMH * IMW)

typedef unsigned long long ull;

// ---------------- scratch (device globals; no allocation allowed) ----------
__device__ float  g_imgn[3 * IMH * IMW];   // normalized planar image (C,H,W)
__device__ float  g_x1[NBOX * 28 * 121];   // after conv1+pool  [28][11][11]
__device__ float  g_x2[NBOX * 48 * 16];    // after conv2+pool  [48][4][4]
__device__ float  g_x3[NBOX * 576];        // after conv3 flat  [64*3*3]
__device__ float  g_w4t[576 * 128];        // transposed lin4 weights
__device__ ulonglong2 g_w2q[28 * 9 * 12];  // conv2 weights, both co-pairs packed
__device__ float  g_w3t[48 * 64 * 4];      // conv3 weights [ci][co][4] (coalesced)
__device__ float4 g_boxes[NBOX];
__device__ float  g_scores[NBOX];
__device__ int    g_sortidx[NBOX];
__device__ float4 g_sboxes[NBOX];
__device__ int    g_M;
__device__ unsigned long long g_mask[NBOX * 64];

// ---------------- f32x2 packed helpers (sm_103a FFMA2 path) ----------------
__device__ __forceinline__ ull pk(float lo, float hi) {
    ull r; asm("mov.b64 %0, {%1,%2};" : "=l"(r) : "f"(lo), "f"(hi)); return r;
}
__device__ __forceinline__ void upk(ull v, float& lo, float& hi) {
    asm("mov.b64 {%0,%1}, %2;" : "=f"(lo), "=f"(hi) : "l"(v));
}
__device__ __forceinline__ ull ffma2(ull a, ull b, ull c) {
    ull d; asm("fma.rn.f32x2 %0, %1, %2, %3;" : "=l"(d) : "l"(a), "l"(b), "l"(c)); return d;
}

__device__ __forceinline__ int fdiv24(int a) {
    int q = a / 24;
    if ((a % 24) != 0 && a < 0) q--;   // python floor-division semantics
    return q;
}

// ---------------- K0: normalize image (vectorized) + weight prep ------------
__global__ void k_prep(const float* __restrict__ img,
                       const float* __restrict__ w4, const float* __restrict__ w2,
                       const float* __restrict__ w3) {
    int i = blockIdx.x * 256 + threadIdx.x;
    if (i < 576 * 128) {
        int k = i >> 7, j = i & 127;
        g_w4t[i] = w4[j * 576 + k];
    }
    if (i < 3024) {
        int cpg = i % 12, t = i / 12, ci = t / 9, k = t % 9;
        ulonglong2 v;
        v.x = pk(w2[(cpg * 28 + ci) * 9 + k],        w2[((cpg + 24) * 28 + ci) * 9 + k]);
        v.y = pk(w2[((cpg + 12) * 28 + ci) * 9 + k], w2[((cpg + 36) * 28 + ci) * 9 + k]);
        g_w2q[t * 12 + cpg] = v;
    }
    if (i < 12288) {
        int q = i & 3, co = (i >> 2) & 63, ci = i >> 8;
        g_w3t[i] = w3[(co * 48 + ci) * 4 + q];
    }
    // normalize 4 pixels per thread (NPIX divisible by 4)
    if (i < NPIX / 4) {
        const float4* ip = (const float4*)(img + i * 12);
        float4 A = ip[0], B = ip[1], C = ip[2];
        const float o = 127.5f, sc = 0.0078125f;
        float4 R = make_float4((A.x - o) * sc, (A.w - o) * sc, (B.z - o) * sc, (C.y - o) * sc);
        float4 G = make_float4((A.y - o) * sc, (B.x - o) * sc, (B.w - o) * sc, (C.z - o) * sc);
        float4 Bv = make_float4((A.z - o) * sc, (B.y - o) * sc, (C.x - o) * sc, (C.w - o) * sc);
        ((float4*)(g_imgn + i * 4))[0] = R;
        ((float4*)(g_imgn + NPIX + i * 4))[0] = G;
        ((float4*)(g_imgn + 2 * NPIX + i * 4))[0] = Bv;
    }
}

// ---------------- K1: crop+conv1+prelu+maxpool ------------------------------
// block per box, 640 threads, 2 blocks/SM. thread=(cp in 14, s in 22, h in 2):
// channels cp & cp+14, col s, rows h*11..h*11+10. Rolling 3-deep column window.
__global__ void __launch_bounds__(640, 2) k_conv1(const float* __restrict__ bb,
                        const float* __restrict__ w1, const float* __restrict__ b1,
                        const float* __restrict__ a1) {
    extern __shared__ char smem[];
    ull*   s_crop2 = (ull*)smem;                          // 1728 ull (splatted crop)
    float* s_conv  = (float*)(smem + 13824);              // 13552 floats
    ull*   s_wp    = (ull*)(smem + 13824 + 54208);        // 378 ull
    int*   s_ix    = (int*)(smem + 13824 + 54208 + 3024); // 24
    int*   s_iy    = s_ix + 24;                           // 24
    int box = blockIdx.x, tid = threadIdx.x;

    if (tid < 48) {
        int j = tid % 24;
        if (tid < 24) {
            int x1 = (int)bb[box * 4 + 0]; x1 = min(max(x1, 0), IMW);
            int x2 = (int)bb[box * 4 + 2]; x2 = min(max(x2, 0), IMW);
            int v = x1 + fdiv24(j * (x2 - x1));
            s_ix[j] = min(max(v, 0), IMW - 1);
        } else {
            int y1 = (int)bb[box * 4 + 1]; y1 = min(max(y1, 0), IMH);
            int y2 = (int)bb[box * 4 + 3]; y2 = min(max(y2, 0), IMH);
            int v = y1 + fdiv24(j * (y2 - y1));
            s_iy[j] = min(max(v, 0), IMH - 1);
        }
    }
    for (int i = tid; i < 378; i += 640) {
        int cp = i / 27, k = i % 27;
        s_wp[i] = pk(w1[cp * 27 + k], w1[(cp + 14) * 27 + k]);
    }
    __syncthreads();
    for (int i = tid; i < 1728; i += 640) {
        int c = i / 576, rem = i % 576, y = rem / 24, x = rem % 24;
        float v = g_imgn[c * NPIX + s_iy[y] * IMW + s_ix[x]];
        s_crop2[i] = pk(v, v);
    }
    __syncthreads();

    int cp = 0, s = 0, r0 = 0;
    ull acc[11];
    if (tid < 616) {
        cp = tid / 44;
        int rem = tid % 44;
        s = rem >> 1;
        r0 = (rem & 1) * 11;
        ull bv = pk(b1[cp], b1[cp + 14]);
        #pragma unroll
        for (int r = 0; r < 11; r++) acc[r] = bv;
        #pragma unroll
        for (int ci = 0; ci < 3; ci++) {
            const ull* cb = &s_crop2[ci * 576 + r0 * 24 + s];
            const ull* wb = &s_wp[cp * 27 + ci * 9];
            #pragma unroll
            for (int kw = 0; kw < 3; kw++) {
                ull w0 = wb[kw], w1v = wb[3 + kw], w2v = wb[6 + kw];
                ull v0 = cb[0 * 24 + kw];
                ull v1 = cb[1 * 24 + kw];
                #pragma unroll
                for (int r = 0; r < 11; r++) {
                    ull v2 = cb[(r + 2) * 24 + kw];
                    acc[r] = ffma2(v0, w0, acc[r]);
                    acc[r] = ffma2(v1, w1v, acc[r]);
                    acc[r] = ffma2(v2, w2v, acc[r]);
                    v0 = v1; v1 = v2;
                }
            }
        }
    }
    if (tid < 616) {
        float a0 = a1[cp], aH = a1[cp + 14];
        #pragma unroll
        for (int r = 0; r < 11; r++) {
            float lo, hi; upk(acc[r], lo, hi);
            s_conv[cp * 484 + (r0 + r) * 22 + s]        = lo > 0.f ? lo : lo * a0;
            s_conv[(cp + 14) * 484 + (r0 + r) * 22 + s] = hi > 0.f ? hi : hi * aH;
        }
    }
    __syncthreads();
    for (int o = tid; o < 3388; o += 640) {
        int c = o / 121, p = o % 121, ph = p / 11, pw = p % 11;
        float m = -1e30f;
        #pragma unroll
        for (int dr = 0; dr < 3; dr++) {
            int r = 2 * ph - 1 + dr; if (r < 0 || r > 21) continue;
            #pragma unroll
            for (int ds = 0; ds < 3; ds++) {
                int ss = 2 * pw - 1 + ds; if (ss < 0 || ss > 21) continue;
                m = fmaxf(m, s_conv[c * 484 + r * 22 + ss]);
            }
        }
        g_x1[box * 3388 + o] = m;
    }
}

// ---------------- K2: conv2+prelu+maxpool (4-ch threads, LDG.128 weights) ---
__global__ void __launch_bounds__(216, 4) k_conv2(const float* __restrict__ b2,
                                                  const float* __restrict__ a2) {
    __shared__ ull s_in2[3388];
    __shared__ ull s_part[1944];           // h=1 partials; aliased as s_conv after
    float* s_conv = (float*)s_part;        // 3888 floats
    int box = blockIdx.x, tid = threadIdx.x;
    for (int i = tid; i < 3388; i += 216) {
        float v = g_x1[box * 3388 + i];
        s_in2[i] = pk(v, v);
    }
    __syncthreads();
    int half = tid >= 108;
    int t108 = half ? tid - 108 : tid;
    int cpg = t108 / 9, s = t108 % 9;
    ull accA[9], accB[9];
    if (!half) {
        ull bvA = pk(__ldg(&b2[cpg]),      __ldg(&b2[cpg + 24]));
        ull bvB = pk(__ldg(&b2[cpg + 12]), __ldg(&b2[cpg + 36]));
        #pragma unroll
        for (int r = 0; r < 9; r++) { accA[r] = bvA; accB[r] = bvB; }
    } else {
        #pragma unroll
        for (int r = 0; r < 9; r++) { accA[r] = 0ull; accB[r] = 0ull; }
    }
    int ci0 = half ? 14 : 0;
    #pragma unroll 2
    for (int cc = 0; cc < 14; cc++) {
        int ci = ci0 + cc;
        const ulonglong2* wq = &g_w2q[ci * 108 + cpg];
        const ull* ip = &s_in2[ci * 121 + s];
        #pragma unroll
        for (int kw = 0; kw < 3; kw++) {
            ulonglong2 w0 = __ldg(&wq[(0 * 3 + kw) * 12]);
            ulonglong2 w1v = __ldg(&wq[(1 * 3 + kw) * 12]);
            ulonglong2 w2v = __ldg(&wq[(2 * 3 + kw) * 12]);
            #pragma unroll
            for (int t = 0; t < 11; t++) {
                ull sp = ip[t * 11 + kw];
                if (t <= 8) {
                    accA[t] = ffma2(sp, w0.x, accA[t]);
                    accB[t] = ffma2(sp, w0.y, accB[t]);
                }
                if (t >= 1 && t <= 9) {
                    accA[t - 1] = ffma2(sp, w1v.x, accA[t - 1]);
                    accB[t - 1] = ffma2(sp, w1v.y, accB[t - 1]);
                }
                if (t >= 2) {
                    accA[t - 2] = ffma2(sp, w2v.x, accA[t - 2]);
                    accB[t - 2] = ffma2(sp, w2v.y, accB[t - 2]);
                }
            }
        }
    }
    if (half) {
        #pragma unroll
        for (int c = 0; c < 9; c++) {
            s_part[t108 * 18 + c]     = accA[c];
            s_part[t108 * 18 + 9 + c] = accB[c];
        }
    }
    __syncthreads();
    float outv[36];
    if (!half) {
        float aA0 = __ldg(&a2[cpg]),      aA1 = __ldg(&a2[cpg + 24]);
        float aB0 = __ldg(&a2[cpg + 12]), aB1 = __ldg(&a2[cpg + 36]);
        #pragma unroll
        for (int c = 0; c < 9; c++) {
            float lo, hi, plo, phi;
            upk(accA[c], lo, hi);
            upk(s_part[t108 * 18 + c], plo, phi);
            lo += plo; hi += phi;
            outv[c]      = lo > 0.f ? lo : lo * aA0;
            outv[9 + c]  = hi > 0.f ? hi : hi * aA1;
            upk(accB[c], lo, hi);
            upk(s_part[t108 * 18 + 9 + c], plo, phi);
            lo += plo; hi += phi;
            outv[18 + c] = lo > 0.f ? lo : lo * aB0;
            outv[27 + c] = hi > 0.f ? hi : hi * aB1;
        }
    }
    __syncthreads();   // all partial reads done before s_conv overwrites alias
    if (!half) {
        #pragma unroll
        for (int c = 0; c < 9; c++) {
            s_conv[cpg * 81 + c * 9 + s]        = outv[c];
            s_conv[(cpg + 24) * 81 + c * 9 + s] = outv[9 + c];
            s_conv[(cpg + 12) * 81 + c * 9 + s] = outv[18 + c];
            s_conv[(cpg + 36) * 81 + c * 9 + s] = outv[27 + c];
        }
    }
    __syncthreads();
    for (int o = tid; o < 768; o += 216) {
        int co = o / 16, p = o % 16, ph = p / 4, pw = p % 4;
        float m = -1e30f;
        #pragma unroll
        for (int dr = 0; dr < 3; dr++)
            #pragma unroll
            for (int ds = 0; ds < 3; ds++)
                m = fmaxf(m, s_conv[co * 81 + (2 * ph + dr) * 9 + (2 * pw + ds)]);
        g_x2[box * 768 + o] = m;
    }
}

// ---------------- K3: conv3+prelu (f32x2 box-pairs, 4 boxes/block) ----------
// 4 boxes per block, 128 threads: thread = (pair pr 0..1, co 0..63) computes
// channel co for boxes box0+pr and box0+pr+2 in packed f32x2.
__global__ void __launch_bounds__(128) k_conv3(const float* __restrict__ b3,
                                               const float* __restrict__ a3) {
    __shared__ ull s_in2[1536];   // [pr][ci][16] packed (box0+pr, box0+pr+2)
    int tid = threadIdx.x;
    int pr = tid >> 6, co = tid & 63;
    int base = blockIdx.x * 3072;
    for (int i = tid; i < 1536; i += 128)
        s_in2[i] = pk(g_x2[base + i], g_x2[base + 1536 + i]);
    __syncthreads();

    ull acc[9];
    float bvs = __ldg(&b3[co]);
    ull bv = pk(bvs, bvs);
    #pragma unroll
    for (int r = 0; r < 9; r++) acc[r] = bv;

    const float4* wt = (const float4*)g_w3t;
    const ulonglong2* qb = (const ulonglong2*)&s_in2[pr * 768];
    #pragma unroll 2
    for (int ci = 0; ci < 48; ci++) {
        float4 w = __ldg(&wt[ci * 64 + co]);
        ull wx = pk(w.x, w.x), wy = pk(w.y, w.y), wz = pk(w.z, w.z), ww = pk(w.w, w.w);
        ull v[4][4];
        #pragma unroll
        for (int r = 0; r < 4; r++) {
            ulonglong2 p0 = qb[ci * 8 + r * 2];
            ulonglong2 p1 = qb[ci * 8 + r * 2 + 1];
            v[r][0] = p0.x; v[r][1] = p0.y; v[r][2] = p1.x; v[r][3] = p1.y;
        }
        #pragma unroll
        for (int r = 0; r < 3; r++)
            #pragma unroll
            for (int s = 0; s < 3; s++) {
                ull t = acc[r * 3 + s];
                t = ffma2(v[r][s],         wx, t);
                t = ffma2(v[r][s + 1],     wy, t);
                t = ffma2(v[r + 1][s],     wz, t);
                t = ffma2(v[r + 1][s + 1], ww, t);
                acc[r * 3 + s] = t;
            }
    }
    float av = __ldg(&a3[co]);
    int box = blockIdx.x * 4 + pr;
    #pragma unroll
    for (int r = 0; r < 9; r++) {
        float lo, hi; upk(acc[r], lo, hi);
        g_x3[box * 576 + co * 9 + r]       = lo > 0.f ? lo : lo * av;
        g_x3[(box + 2) * 576 + co * 9 + r] = hi > 0.f ? hi : hi * av;
    }
}

// ---------------- K4: lin4+prelu, lin5a/b, softmax, box regression ----------
// block = 16 boxes, 256 threads = two independent 8-box halves (half = tid>>7);
// each half runs the proven 4-accumulator fc on its own smem region.
__global__ void __launch_bounds__(256) k_fc(const float* __restrict__ bb,
                     const float* __restrict__ b4, const float* __restrict__ a4,
                     const float* __restrict__ w5a, const float* __restrict__ b5a,
                     const float* __restrict__ w5b, const float* __restrict__ b5b) {
    __shared__ ull   s_x3p[2][4 * 576];   // [half][bp][k]
    __shared__ float s_feat[16 * 128];
    __shared__ float s_dot[96];
    int tid = threadIdx.x;
    int half = tid >> 7, j = tid & 127;
    int boxbase = blockIdx.x * 16 + half * 8;
    #pragma unroll
    for (int bp = 0; bp < 4; bp++) {
        for (int k = j; k < 576; k += 128) {
            s_x3p[half][bp * 576 + k] = pk(g_x3[(boxbase + bp) * 576 + k],
                                           g_x3[(boxbase + bp + 4) * 576 + k]);
        }
    }
    __syncthreads();
    {
        ull acc[4];
        float bvs = b4[j];
        ull bv = pk(bvs, bvs);
        #pragma unroll
        for (int b = 0; b < 4; b++) acc[b] = bv;
        const ull* xp = s_x3p[half];
        #pragma unroll 4
        for (int k = 0; k < 576; k++) {
            float wv = g_w4t[k * 128 + j];
            ull wp2 = pk(wv, wv);
            #pragma unroll
            for (int b = 0; b < 4; b++) acc[b] = ffma2(xp[b * 576 + k], wp2, acc[b]);
        }
        float av = a4[j];
        #pragma unroll
        for (int b = 0; b < 4; b++) {
            float lo, hi; upk(acc[b], lo, hi);
            s_feat[(half * 8 + b) * 128 + j]       = lo > 0.f ? lo : lo * av;
            s_feat[(half * 8 + b + 4) * 128 + j]   = hi > 0.f ? hi : hi * av;
        }
    }
    __syncthreads();
    int warp = tid >> 5, lane = tid & 31;
    for (int d = warp; d < 96; d += 8) {
        int b = d / 6, o = d % 6;
        const float* wrow = (o < 2) ? &w5a[o * 128] : &w5b[(o - 2) * 128];
        float p = 0.f;
        #pragma unroll
        for (int kk = 0; kk < 4; kk++)
            p += s_feat[b * 128 + lane + kk * 32] * __ldg(&wrow[lane + kk * 32]);
        #pragma unroll
        for (int off = 16; off > 0; off >>= 1) p += __shfl_xor_sync(0xffffffffu, p, off);
        if (lane == 0) s_dot[d] = p;
    }
    __syncthreads();
    if (tid < 16) {
        int b = tid, gb = blockIdx.x * 16 + b;
        float z0 = s_dot[b * 6 + 0] + b5a[0];
        float z1 = s_dot[b * 6 + 1] + b5a[1];
        float mz = fmaxf(z0, z1);
        float e0 = expf(z0 - mz), e1 = expf(z1 - mz);
        g_scores[gb] = e1 / (e0 + e1);
        float4 B = ((const float4*)bb)[gb];
        float bw = B.z - B.x, bh = B.w - B.y;
        float4 nb;
        nb.x = B.x + (s_dot[b * 6 + 2] + b5b[0]) * bw;
        nb.y = B.y + (s_dot[b * 6 + 3] + b5b[1]) * bh;
        nb.z = B.z + (s_dot[b * 6 + 4] + b5b[2]) * bw;
        nb.w = B.w + (s_dot[b * 6 + 5] + b5b[3]) * bh;
        g_boxes[gb] = nb;
    }
}

// ---------------- K5: compact valid + adaptive bitonic sort -----------------
__global__ void k_sort() {
    __shared__ unsigned long long key[4096];
    __shared__ int s_cnt, s_P;
    int tid = threadIdx.x;
    if (tid == 0) s_cnt = 0;
    __syncthreads();
    for (int i = tid; i < 4096; i += 1024) {
        float sc = g_scores[i];
        if (sc >= 0.7f) {
            unsigned u = __float_as_uint(sc);
            unsigned m = (u & 0x80000000u) ? ~u : (u | 0x80000000u);  // monotone map
            int pos = atomicAdd(&s_cnt, 1);
            key[pos] = ((unsigned long long)(~m) << 32) | (unsigned)i;  // asc = desc score, asc idx
        }
    }
    __syncthreads();
    int M = s_cnt;
    if (tid == 0) {
        g_M = M;
        int P = 2;
        while (P < M) P <<= 1;
        s_P = P;
    }
    __syncthreads();
    int P = s_P;
    for (int i = M + tid; i < P; i += 1024) key[i] = 0xFFFFFFFFFFFFFFFFull;
    __syncthreads();
    for (int k = 2; k <= P; k <<= 1) {
        for (int j = k >> 1; j > 0; j >>= 1) {
            for (int t = tid; t < P; t += 1024) {
                int ixj = t ^ j;
                if (ixj > t) {
                    bool up = ((t & k) == 0);
                    unsigned long long a = key[t], b = key[ixj];
                    if ((a > b) == up) { key[t] = b; key[ixj] = a; }
                }
            }
            __syncthreads();
        }
    }
    for (int i = tid; i < M; i += 1024) {
        int idx = (int)(unsigned)key[i];
        g_sortidx[i] = idx;
        g_sboxes[i] = g_boxes[idx];
    }
}

// ---------------- K6: pairwise IOU bitmask over valid prefix ----------------
__global__ void k_mask() {
    int gid = blockIdx.x * 256 + threadIdx.x;
    int row = gid >> 6, word = gid & 63;
    int M = g_M;
    if (row >= M) return;
    int nw = (M + 63) >> 6;
    if (word >= nw) return;
    float4 bi = g_sboxes[row];
    float ai = fmaxf(bi.z - bi.x, 0.f) * fmaxf(bi.w - bi.y, 0.f);
    unsigned long long m = 0;
    int j0 = word * 64;
    for (int t = 0; t < 64; t++) {
        int j = j0 + t;
        if (j <= row || j >= M) continue;
        float4 bj = g_sboxes[j];
        float xx1 = fmaxf(bi.x, bj.x), yy1 = fmaxf(bi.y, bj.y);
        float xx2 = fminf(bi.z, bj.z), yy2 = fminf(bi.w, bj.w);
        float inter = fmaxf(xx2 - xx1, 0.f) * fmaxf(yy2 - yy1, 0.f);
        float aj = fmaxf(bj.z - bj.x, 0.f) * fmaxf(bj.w - bj.y, 0.f);
        float iou = inter / fmaxf(ai + aj - inter, 1e-12f);
        if (iou > 0.5f) m |= (1ull << t);
    }
    g_mask[row * 64 + word] = m;
}

// ---------------- K7: NMS scan, zero-fill, scatter kept ---------------------
__global__ void k_scan(float* __restrict__ out) {
    __shared__ unsigned char s_keep[4096];
    int tid = threadIdx.x;
    int M = g_M;
    if (tid < 32) {
        ull rlo = 0, rhi = 0;   // lane t owns words t and 32+t (4096 bits)
        ull blo[8], bhi[8];
        #pragma unroll
        for (int k = 0; k < 8; k++) {
            if (k < M) { blo[k] = g_mask[k * 64 + tid]; bhi[k] = g_mask[k * 64 + 32 + tid]; }
        }
        for (int ib = 0; ib < M; ib += 8) {
            #pragma unroll
            for (int k = 0; k < 8; k++) {
                int i = ib + k;
                if (i < M) {
                    ull clo = blo[k], chi = bhi[k];
                    if (i + 8 < M) {
                        blo[k] = g_mask[(i + 8) * 64 + tid];
                        bhi[k] = g_mask[(i + 8) * 64 + 32 + tid];
                    }
                    int w = i >> 6, b = i & 63;
                    ull cand = (w < 32) ? rlo : rhi;
                    ull rv = __shfl_sync(0xffffffffu, cand, w & 31);
                    int sup = (int)((rv >> b) & 1ull);
                    if (!sup) { rlo |= clo; rhi |= chi; }
                    if (tid == 0) s_keep[i] = (unsigned char)(!sup);
                }
            }
        }
    }
    __syncthreads();
    for (int i = tid; i < 4096; i += blockDim.x)
        ((float4*)out)[i] = make_float4(0.f, 0.f, 0.f, 0.f);
    __syncthreads();
    for (int i = tid; i < M; i += blockDim.x) {
        if (s_keep[i]) ((float4*)out)[g_sortidx[i]] = g_sboxes[i];
    }
}

// ---------------- launch ----------------------------------------------------
extern "C" void kernel_launch(void* const* d_in, const int* in_sizes, int n_in,
                              void* d_out, int out_size) {
    const float* img  = (const float*)d_in[0];
    const float* bb   = (const float*)d_in[1];
    const float* w1   = (const float*)d_in[2];
    const float* b1   = (const float*)d_in[3];
    const float* a1   = (const float*)d_in[4];
    const float* w2   = (const float*)d_in[5];
    const float* b2   = (const float*)d_in[6];
    const float* a2   = (const float*)d_in[7];
    const float* w3   = (const float*)d_in[8];
    const float* b3   = (const float*)d_in[9];
    const float* a3   = (const float*)d_in[10];
    const float* w4   = (const float*)d_in[11];
    const float* b4   = (const float*)d_in[12];
    const float* a4   = (const float*)d_in[13];
    const float* w5a  = (const float*)d_in[14];
    const float* b5a  = (const float*)d_in[15];
    const float* w5b  = (const float*)d_in[16];
    const float* b5b  = (const float*)d_in[17];
    float* out = (float*)d_out;

    static int smem_set = 0;
    if (!smem_set) {
        cudaFuncSetAttribute(k_conv1, cudaFuncAttributeMaxDynamicSharedMemorySize, 71296);
        smem_set = 1;
    }

    k_prep <<<(NPIX / 4 + 255) / 256, 256>>>(img, w4, w2, w3);
    k_conv1<<<NBOX, 640, 71296>>>(bb, w1, b1, a1);
    k_conv2<<<NBOX, 216>>>(b2, a2);
    k_conv3<<<NBOX / 4, 128>>>(b3, a3);
    k_fc   <<<NBOX / 16, 256>>>(bb, b4, a4, w5a, b5a, w5b, b5b);
    k_sort <<<1, 1024>>>();
    k_mask <<<1024, 256>>>();
    k_scan <<<1, 256>>>(out);
}